// round 4
// baseline (speedup 1.0000x reference)
#include <cuda_runtime.h>
#include <cstdint>

#define N 8400
#define WORDS 132          // ceil(8400/64)
#define SCORE_THR 0.5f
#define IOU_THR 0.5f
#define GRID 136           // <= 148 SMs: all blocks co-resident (wave 1)
#define NT 256

typedef unsigned long long u64;

// ---- persistent device state (allocation-free rule) ----
__device__ int g_vcount = 0;
__device__ int g_bar_arrive = 0;
__device__ volatile int g_bar_release = 0;
__device__ int g_bar_exit = 0;
__device__ u64 g_vkey[N];
__device__ float4 g_vbox[N];
__device__ float g_vscore[N];
__device__ int g_rankp[8][N];
__device__ float4 g_sbox[N];
__device__ float g_sscore[N];
__device__ u64 g_mask[N][WORDS];

// Software grid barrier. Safe because GRID < #SMs (all CTAs co-resident).
// Cumulative arrive counter: barrier `gen` releases when count hits gen*GRID.
__device__ __forceinline__ void gbar(int gen) {
    __syncthreads();
    if (threadIdx.x == 0) {
        __threadfence();                       // publish this block's writes
        int prev = atomicAdd(&g_bar_arrive, 1);
        if (prev == gen * GRID - 1) {
            g_bar_release = gen;               // last arriver releases
        } else {
            while (g_bar_release < gen) { }    // volatile spin
        }
        __threadfence();                       // acquire
    }
    __syncthreads();
}

__global__ __launch_bounds__(NT) void k_all(const float* __restrict__ in,
                                            float* __restrict__ out) {
    __shared__ __align__(16) char smraw[8448];  // phase-shared scratch
    __shared__ int s_nk;
    int tid = threadIdx.x;
    int bid = blockIdx.x;
    int gtid = bid * NT + tid;

    // ---------------- Phase 1: decode + compact valid (warp-agg atomic) ----
    {
        int a = gtid;
        int lane = tid & 31;
        bool valid = false;
        float4 b = make_float4(0.f, 0.f, 0.f, 0.f);
        float s = 0.f;
        u64 key = 0ull;
        if (a < N) {
            float cx = in[a];
            float cy = in[N + a];
            float w  = in[2 * N + a];
            float h  = in[3 * N + a];
            s = in[4 * N + a];
            float hw = __fmul_rn(w, 0.5f);
            float hh = __fmul_rn(h, 0.5f);
            b.x = __fsub_rn(cx, hw);
            b.y = __fsub_rn(cy, hh);
            b.z = __fadd_rn(cx, hw);
            b.w = __fadd_rn(cy, hh);
            valid = (s >= SCORE_THR);
            // unique key: descending score, ascending-index tie-break
            key = (((u64)__float_as_uint(s)) << 14) | (u64)(16383 - a);
        }
        unsigned m = __ballot_sync(0xffffffffu, valid);
        if (m != 0u) {
            int leader = __ffs(m) - 1;
            int base = 0;
            if (lane == leader) base = atomicAdd(&g_vcount, __popc(m));
            base = __shfl_sync(0xffffffffu, base, leader);
            if (valid) {
                int pos = base + __popc(m & ((1u << lane) - 1u));
                g_vkey[pos]   = key;
                g_vbox[pos]   = b;
                g_vscore[pos] = s;
            }
        }
    }
    gbar(1);
    int V = *(volatile int*)&g_vcount;

    // ---------------- Phase 2: rank partials (i-blocks x 8 j-chunks) -------
    {
        u64* sk = (u64*)smraw;                 // up to 1050 keys (8.4KB)
        int IB = (V + NT - 1) / NT;
        int CH = (V + 7) / 8;
        int ntasks = IB * 8;
        for (int task = bid; task < ntasks; task += GRID) {
            int ib = task % IB;
            int jb = task / IB;
            int jlo = jb * CH;
            int mlen = min(jlo + CH, V) - jlo;
            __syncthreads();                   // protect sk reuse across tasks
            for (int d = tid; d < mlen; d += NT)
                sk[d] = g_vkey[jlo + d];
            __syncthreads();
            int p = ib * NT + tid;
            u64 kp = (p < V) ? g_vkey[p] : 0ull;
            int cnt = 0;
#pragma unroll 8
            for (int d = 0; d < mlen; ++d)
                cnt += (sk[d] > kp) ? 1 : 0;
            if (p < V) g_rankp[jb][p] = cnt;
        }
    }
    gbar(2);

    // ---------------- Phase 3: sum partials + scatter -----------------------
    for (int p = gtid; p < V; p += GRID * NT) {
        int r = 0;
#pragma unroll
        for (int y = 0; y < 8; ++y) r += g_rankp[y][p];
        g_sbox[r]   = g_vbox[p];
        g_sscore[r] = g_vscore[p];
    }
    gbar(3);

    // ---------------- Phase 4: IoU bitmask (128x128 triangle tiles) --------
    {
        float4* cbox  = (float4*)smraw;               // 128 * 16B
        float*  carea = (float*)(smraw + 128 * 16);   // 128 * 4B
        int Tv = (V + 127) >> 7;
        int ntasks = Tv * (Tv + 1) / 2;
        for (int task = bid; task < ntasks; task += GRID) {
            // linear -> (rb, cb) with cb >= rb
            int t2 = task, rb = 0;
            while (t2 >= Tv - rb) { t2 -= Tv - rb; rb++; }
            int cb = rb + t2;
            __syncthreads();                   // protect smem reuse
            if (tid < 128) {
                int j = cb * 128 + tid;
                if (j < V) {
                    float4 b = g_sbox[j];
                    cbox[tid] = b;
                    carea[tid] = __fmul_rn(__fsub_rn(b.z, b.x),
                                           __fsub_rn(b.w, b.y));
                } else {
                    cbox[tid] = make_float4(0.f, 0.f, 0.f, 0.f);
                    carea[tid] = 0.f;
                }
            }
            __syncthreads();
            int row = tid & 127;
            int half = tid >> 7;
            int i = rb * 128 + row;
            if (i < V) {
                float4 bi = g_sbox[i];
                float ai = __fmul_rn(__fsub_rn(bi.z, bi.x),
                                     __fsub_rn(bi.w, bi.y));
                int cbase = half * 64;
                int wordbase = cb * 128 + cbase;
                int dstart = max(0, i + 1 - wordbase);   // strict upper tri
                u64 bits = 0ull;
                for (int d = dstart; d < 64; ++d) {
                    float4 bj = cbox[cbase + d];
                    float ltx = fmaxf(bi.x, bj.x);
                    float lty = fmaxf(bi.y, bj.y);
                    float rbx = fminf(bi.z, bj.z);
                    float rby = fminf(bi.w, bj.w);
                    float wx = fmaxf(__fsub_rn(rbx, ltx), 0.0f);
                    float wy = fmaxf(__fsub_rn(rby, lty), 0.0f);
                    float inter = __fmul_rn(wx, wy);
                    float uni = __fsub_rn(__fadd_rn(ai, carea[cbase + d]), inter);
                    float den = fmaxf(uni, 1e-9f);
                    // guard-banded division screen (bit-exact decisions)
                    bool hit;
                    if (inter > __fmul_rn(0.5005f, den))      hit = true;
                    else if (inter < __fmul_rn(0.4995f, den)) hit = false;
                    else hit = (__fdiv_rn(inter, den) > IOU_THR);
                    if (hit) bits |= (1ull << d);
                }
                g_mask[i][cb * 2 + half] = bits;
            }
        }
    }
    gbar(4);

    // ---------------- Phase 5: block 0 only — greedy reduce + output -------
    if (bid != 0) {
        __syncthreads();
        if (tid == 0) atomicAdd(&g_bar_exit, 1);   // signal retirement
        return;
    }

    u64* remv = (u64*)smraw;                        // 132 * 8B
    u64* diag = (u64*)(smraw + WORDS * 8);          // 2 * 64 * 8B
    int* rows = (int*)(smraw + WORDS * 8 + 1024);   // 64 * 4B
    int T = (V + 63) >> 6;
    __syncthreads();
    for (int w = tid; w < WORDS; w += NT) remv[w] = 0ull;
    if (tid < 64) diag[tid] = (T > 0 && tid < V) ? g_mask[tid][0] : 0ull;
    __syncthreads();

    for (int t = 0; t < T; ++t) {
        int buf = t & 1;
        if (tid >= 64 && tid < 128) {               // prefetch next diagonal
            int tn = t + 1;
            u64 v = 0ull;
            if (tn < T) {
                int i = tn * 64 + (tid - 64);
                if (i < V) v = g_mask[i][tn];
            }
            diag[(buf ^ 1) * 64 + (tid - 64)] = v;
        }
        if (tid == 0) {
            u64 cur = remv[t];
            int rem = V - t * 64;
            if (rem < 64) cur |= (~0ull) << rem;    // rows >= V removed
            u64 expl = cur;
            int nk = 0;
            while (~expl) {
                int b = __ffsll(~expl) - 1;         // lowest undecided = KEPT
                rows[nk++] = t * 64 + b;
                cur |= diag[buf * 64 + b];
                expl = cur | ((b == 63) ? ~0ull : ((2ull << b) - 1ull));
            }
            remv[t] = cur;
            s_nk = nk;
        }
        __syncthreads();
        int nk = s_nk;
        int nwords = T - 1 - t;
        int total = nk * nwords;
        for (int q = tid; q < total; q += NT) {
            int w = t + 1 + (q % nwords);
            int r = rows[q / nwords];
            u64 m = g_mask[r][w];
            if (m) atomicOr(&remv[w], m);
        }
        __syncthreads();
    }

    // output: kept -> [x1,y1,x2,y2,score], else zeros
    for (int p = tid; p < N; p += NT) {
        bool kept = (p < V) && !((remv[p >> 6] >> (p & 63)) & 1ull);
        float4 b = kept ? g_sbox[p] : make_float4(0.f, 0.f, 0.f, 0.f);
        float s = kept ? g_sscore[p] : 0.f;
        out[p * 5 + 0] = b.x;
        out[p * 5 + 1] = b.y;
        out[p * 5 + 2] = b.z;
        out[p * 5 + 3] = b.w;
        out[p * 5 + 4] = s;
    }

    // reset persistent state for the next graph replay — only after every
    // other block has retired (so nobody is still spinning on g_bar_release)
    __syncthreads();
    if (tid == 0) {
        while (*(volatile int*)&g_bar_exit < GRID - 1) { }
        g_bar_exit = 0;
        g_bar_arrive = 0;
        g_bar_release = 0;
        g_vcount = 0;
        __threadfence();
    }
}

extern "C" void kernel_launch(void* const* d_in, const int* in_sizes, int n_in,
                              void* d_out, int out_size) {
    const float* in = (const float*)d_in[0];
    float* out = (float*)d_out;
    k_all<<<GRID, NT>>>(in, out);
}